// round 6
// baseline (speedup 1.0000x reference)
#include <cuda_runtime.h>

// NeRF fine sampling, forward-emission formulation.
//   inputs : rays_o [N,3], rays_d [N,3], z_vals [N,64] (sorted), weights [N,64]
//   outputs: pts [N,192,3], z_all [N,192]  (d_out = [pts | z_all])
// One warp per ray. No binary searches: each CDF bin emits its contiguous
// range of the fixed u-grid samples; merge ranks computed from bin indices.

#define NS        64
#define NI        128
#define NALL      192
#define RPB       8
#define FULLMASK  0xffffffffu
#define INV127    (1.0f / 127.0f)

// per-warp smem layout (floats)
#define OFF_Z     0     // 64
#define OFF_MID   64    // 64  (mid[0..62] real, mid[63] = mid[62] pad)
#define OFF_CDF   128   // 65  (cdf[0..62] real, cdf[63]=cdf[64]=2.0 pads)
#define OFF_SAMP  196   // 128
#define OFF_ALL   324   // 192 (16B aligned: 324*4 = 1296)
#define OFF_ST    516   // 64 ints (bin start table)
#define STRIDE    584

// first sample index s with u_s = s*INV127 >= c   (exact, with fixup)
__device__ __forceinline__ int u_lo(float c) {
    int s = (int)ceilf(c * 127.0f);
    s = max(0, min(s, 128));
    while (s < 128 && (float)s * INV127 < c) s++;
    while (s > 0 && (float)(s - 1) * INV127 >= c) s--;
    return s;
}

__global__ __launch_bounds__(256, 7)
void nerf_fine_sample_kernel(
    const float* __restrict__ rays_o,
    const float* __restrict__ rays_d,
    const float* __restrict__ z_vals,
    const float* __restrict__ weights,
    float* __restrict__ out_pts,   // [N,192,3]
    float* __restrict__ out_z,     // [N,192]
    int n_rays,
    int write_pts,
    int write_z)
{
    __shared__ float smem[RPB * STRIDE];

    const int warp = threadIdx.x >> 5;
    const int lane = threadIdx.x & 31;
    const int ray  = blockIdx.x * RPB + warp;
    if (ray >= n_rays) return;

    float* base   = smem + warp * STRIDE;
    float* s_z    = base + OFF_Z;
    float* s_mid  = base + OFF_MID;
    float* s_cdf  = base + OFF_CDF;
    float* s_samp = base + OFF_SAMP;
    float* s_all  = base + OFF_ALL;
    int*   s_st   = (int*)(base + OFF_ST);

    // ---- load z_vals, compute mids -------------------------------------
    const float* zr = z_vals + (size_t)ray * NS;
    const float z0 = zr[lane];
    const float z1 = zr[lane + 32];
    s_z[lane]      = z0;
    s_z[lane + 32] = z1;
    __syncwarp();

    s_mid[lane] = 0.5f * (s_z[lane] + s_z[lane + 1]);
    if (lane < 31)
        s_mid[lane + 32] = 0.5f * (s_z[lane + 32] + s_z[lane + 33]);
    else
        s_mid[63] = 0.5f * (s_z[62] + z1);   // pad = mid[62]; no shfl (UB fix)

    // ---- weights -> pdf -> cdf (warp inclusive scan over 62 values) ----
    const float* wr = weights + (size_t)ray * NS;
    float a = wr[1 + lane] + 1e-5f;                          // w[0..31]
    float b = (lane < 30) ? (wr[33 + lane] + 1e-5f) : 0.0f;  // w[32..61]

    #pragma unroll
    for (int off = 1; off < 32; off <<= 1) {
        float v = __shfl_up_sync(FULLMASK, a, off);
        if (lane >= off) a += v;
    }
    float totA = __shfl_sync(FULLMASK, a, 31);
    #pragma unroll
    for (int off = 1; off < 32; off <<= 1) {
        float v = __shfl_up_sync(FULLMASK, b, off);
        if (lane >= off) b += v;
    }
    b += totA;
    const float wsum = __shfl_sync(FULLMASK, b, 31);
    const float inv  = 1.0f / wsum;

    // cdf[0..62] real; cdf[63]=cdf[64]=2.0 sentinels (empty bins beyond)
    if (lane == 0)  s_cdf[0]  = 0.0f;
    if (lane == 31) { s_cdf[63] = 2.0f; s_cdf[64] = 2.0f; }
    s_cdf[lane + 1] = a * inv;                 // cdf[1..32]
    if (lane < 30) s_cdf[lane + 33] = b * inv; // cdf[33..62]
    __syncwarp();

    // ---- forward emission: lane handles bins 2*lane and 2*lane+1 -------
    {
        const int k0 = 2 * lane;
        const float c0 = s_cdf[k0], c1 = s_cdf[k0 + 1], c2 = s_cdf[k0 + 2];
        const float m0 = s_mid[k0];
        const float m1 = s_mid[k0 + 1];
        const float m2 = s_mid[min(k0 + 2, 63)];
        const float zkA = s_z[k0 + 1];
        const float zkB = s_z[min(k0 + 2, 63)];

        const int b0 = u_lo(c0);
        const int b1 = u_lo(c1);
        const int b2 = u_lo(c2);
        s_st[k0]     = b0;
        s_st[k0 + 1] = b1;

        // bin k0: u in [c0, c1)
        {
            const float den  = c1 - c0;
            const float rden = (den < 1e-5f) ? 1.0f : __fdividef(1.0f, den);
            const float dba  = m1 - m0;
            for (int s = b0; s < b1; s++) {
                const float u = (float)s * INV127;
                float v = fmaf((u - c0) * rden, dba, m0);
                v = fminf(v, m1);                  // containment guard
                const int r = s + k0 + 1 + ((zkA <= v) ? 1 : 0);
                s_samp[s] = v;
                s_all[r]  = v;
            }
        }
        // bin k0+1: u in [c1, c2)
        {
            const float den  = c2 - c1;
            const float rden = (den < 1e-5f) ? 1.0f : __fdividef(1.0f, den);
            const float dba  = m2 - m1;
            for (int s = b1; s < b2; s++) {
                const float u = (float)s * INV127;
                float v = fmaf((u - c1) * rden, dba, m1);
                v = fminf(v, m2);                  // containment guard
                const int r = s + k0 + 2 + ((zkB <= v) ? 1 : 0);
                s_samp[s] = v;
                s_all[r]  = v;
            }
        }
    }
    __syncwarp();

    // ---- place z_vals into merged array --------------------------------
    #pragma unroll
    for (int t = 0; t < 2; t++) {
        const int   i  = lane + 32 * t;
        const float zi = t ? z1 : z0;
        const int Sprev = (i == 0) ? 0 : s_st[i - 1];
        const int Scur  = s_st[i];
        int cnt = 0;
        for (int j = Sprev; j < Scur; j++)
            cnt += (s_samp[j] < zi) ? 1 : 0;
        s_all[i + Sprev + cnt] = zi;
    }
    __syncwarp();

    // ---- outputs: vectorized float4 streaming stores -------------------
    const float ox = rays_o[ray * 3 + 0];
    const float oy = rays_o[ray * 3 + 1];
    const float oz = rays_o[ray * 3 + 2];
    const float dx = rays_d[ray * 3 + 0];
    const float dy = rays_d[ray * 3 + 1];
    const float dz = rays_d[ray * 3 + 2];

    if (write_pts) {
        float4* po4 = (float4*)(out_pts + (size_t)ray * (NALL * 3));
        #pragma unroll
        for (int t = 0; t < 5; t++) {
            const int p = lane + 32 * t;         // float4 index, 144 total
            if (t < 4 || lane < 16) {
                const int e0 = 4 * p;
                const int s0 = e0 / 3;
                const int r  = e0 - 3 * s0;
                const float zv0 = s_all[s0];
                const float zv1 = s_all[s0 + 1];
                const float p0x = fmaf(dx, zv0, ox);
                const float p0y = fmaf(dy, zv0, oy);
                const float p0z = fmaf(dz, zv0, oz);
                const float p1x = fmaf(dx, zv1, ox);
                const float p1y = fmaf(dy, zv1, oy);
                const float p1z = fmaf(dz, zv1, oz);
                float4 v;
                v.x = (r == 0) ? p0x : ((r == 1) ? p0y : p0z);
                v.y = (r == 0) ? p0y : ((r == 1) ? p0z : p1x);
                v.z = (r == 0) ? p0z : ((r == 1) ? p1x : p1y);
                v.w = (r == 0) ? p1x : ((r == 1) ? p1y : p1z);
                __stcs(po4 + p, v);
            }
        }
    }

    if (write_z) {
        float4* zo4 = (float4*)(out_z + (size_t)ray * NALL);
        const float4* sa4 = (const float4*)s_all;
        #pragma unroll
        for (int t = 0; t < 2; t++) {
            const int q = lane + 32 * t;         // 48 float4
            if (t == 0 || lane < 16)
                __stcs(zo4 + q, sa4[q]);
        }
    }
}

extern "C" void kernel_launch(void* const* d_in, const int* in_sizes, int n_in,
                              void* d_out, int out_size)
{
    const float* rays_o  = (const float*)d_in[0];
    const float* rays_d  = (const float*)d_in[1];
    const float* z_vals  = (const float*)d_in[2];
    const float* weights = (const float*)d_in[3];

    const int n_rays = in_sizes[0] / 3;

    const long long pts_elems = (long long)n_rays * NALL * 3;
    const long long z_elems   = (long long)n_rays * NALL;

    const int write_pts = (out_size >= pts_elems) ? 1 : 0;
    const int write_z   = (out_size >= pts_elems + z_elems) ? 1 : 0;

    float* out_pts = (float*)d_out;
    float* out_z   = out_pts + pts_elems;

    dim3 grid((n_rays + RPB - 1) / RPB);
    nerf_fine_sample_kernel<<<grid, 256>>>(
        rays_o, rays_d, z_vals, weights, out_pts, out_z, n_rays,
        write_pts, write_z);
}

// round 7
// speedup vs baseline: 1.4018x; 1.4018x over previous
#include <cuda_runtime.h>

// NeRF fine sampling — hybrid: one binary search per lane + cached linear
// advance over 4 consecutive samples; merge ranks from bin indices.
//   inputs : rays_o [N,3], rays_d [N,3], z_vals [N,64] (sorted), weights [N,64]
//   outputs: pts [N,192,3], z_all [N,192]  (d_out = [pts | z_all])

#define NS        64
#define NI        128
#define NALL      192
#define RPB       8
#define FULLMASK  0xffffffffu
#define INV127    (1.0f / 127.0f)

// per-warp smem layout (floats)
#define OFF_Z     0     // 64
#define OFF_MID   64    // 64  (mid[0..62], mid[63]=mid[62] pad)
#define OFF_CDF   128   // 64  (cdf[0..62], cdf[63]=+INF sentinel)
#define OFF_SAMP  192   // 128 (16B aligned)
#define OFF_ALL   320   // 192 (16B aligned)
#define OFF_ST    512   // 64 ints (bin start table)
#define STRIDE    576

// count of a[0..63] <= v  (branchless; a[63] sentinel keeps result <= 63)
__device__ __forceinline__ int cnt_le_64(const float* __restrict__ a, float v) {
    int pos = 0;
    #pragma unroll
    for (int step = 32; step >= 1; step >>= 1)
        if (a[pos + step - 1] <= v) pos += step;
    if (a[pos] <= v) pos++;
    return pos;
}

// first sample index s with u_s = s*INV127 >= c  (exact, with fixup)
__device__ __forceinline__ int u_lo(float c) {
    int s = (int)ceilf(c * 127.0f);
    s = max(0, min(s, 128));
    while (s < 128 && (float)s * INV127 < c) s++;
    while (s > 0 && (float)(s - 1) * INV127 >= c) s--;
    return s;
}

__global__ __launch_bounds__(256, 7)
void nerf_fine_sample_kernel(
    const float* __restrict__ rays_o,
    const float* __restrict__ rays_d,
    const float* __restrict__ z_vals,
    const float* __restrict__ weights,
    float* __restrict__ out_pts,   // [N,192,3]
    float* __restrict__ out_z,     // [N,192]
    int n_rays,
    int write_pts,
    int write_z)
{
    __shared__ float smem[RPB * STRIDE];

    const int warp = threadIdx.x >> 5;
    const int lane = threadIdx.x & 31;
    const int ray  = blockIdx.x * RPB + warp;
    if (ray >= n_rays) return;

    float* base   = smem + warp * STRIDE;
    float* s_z    = base + OFF_Z;
    float* s_mid  = base + OFF_MID;
    float* s_cdf  = base + OFF_CDF;
    float* s_samp = base + OFF_SAMP;
    float* s_all  = base + OFF_ALL;
    int*   s_st   = (int*)(base + OFF_ST);

    // ---- load z_vals, compute mids -------------------------------------
    const float* zr = z_vals + (size_t)ray * NS;
    const float z0 = zr[lane];
    const float z1 = zr[lane + 32];
    s_z[lane]      = z0;
    s_z[lane + 32] = z1;
    __syncwarp();

    s_mid[lane] = 0.5f * (s_z[lane] + s_z[lane + 1]);
    if (lane < 31)
        s_mid[lane + 32] = 0.5f * (s_z[lane + 32] + s_z[lane + 33]);
    else
        s_mid[63] = 0.5f * (s_z[62] + z1);   // pad = mid[62] (finite; no shfl)

    // ---- weights -> pdf -> cdf (warp inclusive scan over 62 values) ----
    const float* wr = weights + (size_t)ray * NS;
    float a = wr[1 + lane] + 1e-5f;                          // w[0..31]
    float b = (lane < 30) ? (wr[33 + lane] + 1e-5f) : 0.0f;  // w[32..61]

    #pragma unroll
    for (int off = 1; off < 32; off <<= 1) {
        float v = __shfl_up_sync(FULLMASK, a, off);
        if (lane >= off) a += v;
    }
    float totA = __shfl_sync(FULLMASK, a, 31);
    #pragma unroll
    for (int off = 1; off < 32; off <<= 1) {
        float v = __shfl_up_sync(FULLMASK, b, off);
        if (lane >= off) b += v;
    }
    b += totA;
    const float wsum = __shfl_sync(FULLMASK, b, 31);
    const float inv  = 1.0f / wsum;

    if (lane == 0)  s_cdf[0]  = 0.0f;
    if (lane == 31) s_cdf[63] = __int_as_float(0x7f800000);  // +INF sentinel
    s_cdf[lane + 1] = a * inv;                 // cdf[1..32]
    if (lane < 30) s_cdf[lane + 33] = b * inv; // cdf[33..62]
    __syncwarp();

    // ---- bin-start table: st[i] = first sample index in bins >= i ------
    {
        const int i0 = 2 * lane;
        s_st[i0]     = u_lo(s_cdf[i0]);
        s_st[i0 + 1] = (lane == 31) ? 128 : u_lo(s_cdf[i0 + 1]);
    }

    // ---- sampling: lane owns samples 4*lane .. 4*lane+3 ----------------
    {
        const int   s0 = 4 * lane;
        const float u0 = (float)s0 * INV127;

        int k = cnt_le_64(s_cdf, u0) - 1;        // bin of sample s0 (0..62)
        float cl = s_cdf[k],     ch = s_cdf[k + 1];
        float ml = s_mid[k],     mh = s_mid[k + 1];
        float zn = s_z[k + 1];

        float4 sv;
        float* svp = &sv.x;
        #pragma unroll
        for (int t = 0; t < 4; t++) {
            const float u = (float)(s0 + t) * INV127;
            while (ch <= u) {                    // INF sentinel caps k at 62
                k++;
                cl = ch; ml = mh;
                ch = s_cdf[k + 1];
                mh = s_mid[k + 1];
                zn = s_z[k + 1];
            }
            const float den  = ch - cl;          // may be +INF (k==62) -> rden 0
            const float rden = (den < 1e-5f) ? 1.0f : __fdividef(1.0f, den);
            const float v    = fmaf((u - cl) * rden, mh - ml, ml);
            svp[t] = v;
            const int r = (s0 + t) + k + 1 + ((zn <= v) ? 1 : 0);
            s_all[r] = v;
        }
        ((float4*)s_samp)[lane] = sv;            // STS.128
    }
    __syncwarp();

    // ---- place z_vals: rank i + st[i-1] + #{samp in bin i-1 < z_i} -----
    #pragma unroll
    for (int t = 0; t < 2; t++) {
        const int   i  = lane + 32 * t;
        const float zi = t ? z1 : z0;
        const int Sp = i ? s_st[i - 1] : 0;
        const int Sc = i ? s_st[i]     : 0;
        int cnt = 0;
        for (int j = Sp; j < Sc; j++)
            cnt += (s_samp[j] < zi) ? 1 : 0;
        s_all[i + Sp + cnt] = zi;
    }
    __syncwarp();

    // ---- outputs: vectorized float4 streaming stores -------------------
    const float ox = rays_o[ray * 3 + 0];
    const float oy = rays_o[ray * 3 + 1];
    const float oz = rays_o[ray * 3 + 2];
    const float dx = rays_d[ray * 3 + 0];
    const float dy = rays_d[ray * 3 + 1];
    const float dz = rays_d[ray * 3 + 2];

    if (write_pts) {
        float4* po4 = (float4*)(out_pts + (size_t)ray * (NALL * 3));
        #pragma unroll
        for (int t = 0; t < 5; t++) {
            const int p = lane + 32 * t;         // float4 index, 144 total
            if (t < 4 || lane < 16) {
                const int e0 = 4 * p;
                const int s0 = e0 / 3;
                const int r  = e0 - 3 * s0;
                const float zv0 = s_all[s0];
                const float zv1 = s_all[s0 + 1];
                const float p0x = fmaf(dx, zv0, ox);
                const float p0y = fmaf(dy, zv0, oy);
                const float p0z = fmaf(dz, zv0, oz);
                const float p1x = fmaf(dx, zv1, ox);
                const float p1y = fmaf(dy, zv1, oy);
                const float p1z = fmaf(dz, zv1, oz);
                float4 v;
                v.x = (r == 0) ? p0x : ((r == 1) ? p0y : p0z);
                v.y = (r == 0) ? p0y : ((r == 1) ? p0z : p1x);
                v.z = (r == 0) ? p0z : ((r == 1) ? p1x : p1y);
                v.w = (r == 0) ? p1x : ((r == 1) ? p1y : p1z);
                __stcs(po4 + p, v);
            }
        }
    }

    if (write_z) {
        float4* zo4 = (float4*)(out_z + (size_t)ray * NALL);
        const float4* sa4 = (const float4*)s_all;
        #pragma unroll
        for (int t = 0; t < 2; t++) {
            const int q = lane + 32 * t;         // 48 float4
            if (t == 0 || lane < 16)
                __stcs(zo4 + q, sa4[q]);
        }
    }
}

extern "C" void kernel_launch(void* const* d_in, const int* in_sizes, int n_in,
                              void* d_out, int out_size)
{
    const float* rays_o  = (const float*)d_in[0];
    const float* rays_d  = (const float*)d_in[1];
    const float* z_vals  = (const float*)d_in[2];
    const float* weights = (const float*)d_in[3];

    const int n_rays = in_sizes[0] / 3;

    const long long pts_elems = (long long)n_rays * NALL * 3;
    const long long z_elems   = (long long)n_rays * NALL;

    const int write_pts = (out_size >= pts_elems) ? 1 : 0;
    const int write_z   = (out_size >= pts_elems + z_elems) ? 1 : 0;

    float* out_pts = (float*)d_out;
    float* out_z   = out_pts + pts_elems;

    dim3 grid((n_rays + RPB - 1) / RPB);
    nerf_fine_sample_kernel<<<grid, 256>>>(
        rays_o, rays_d, z_vals, weights, out_pts, out_z, n_rays,
        write_pts, write_z);
}